// round 1
// baseline (speedup 1.0000x reference)
#include <cuda_runtime.h>

#define D_MODEL 1024
#define NH 16
#define DH 64
#define SEQ 2048
#define BATCH 2
#define BH (BATCH * NH)        // 32
#define M_ROWS (BATCH * SEQ)   // 4096
#define N_QKV (3 * NH * DH)    // 3072

// Scratch (no cudaMalloc allowed): Q/K/V in [b,h,s,d] layout, A in [b,s,h,d].
__device__ float g_Q[(size_t)BH * SEQ * DH];
__device__ float g_K[(size_t)BH * SEQ * DH];
__device__ float g_V[(size_t)BH * SEQ * DH];
__device__ float g_A[(size_t)M_ROWS * D_MODEL];

// ---------------------------------------------------------------------------
// GEMM 1: qkv = X @ W_qkv, epilogue de-interleaves (h, d, 3) columns into
// Q/K/V buffers with [b,h,s,d] layout.
// C[M=4096, N=3072] = A[4096,1024] @ B[1024,3072]
// ---------------------------------------------------------------------------
__global__ __launch_bounds__(256) void qkv_gemm_kernel(
    const float* __restrict__ A, const float* __restrict__ B)
{
    const int K = D_MODEL;
    const int N = N_QKV;
    __shared__ float As[16][132];   // padded: 2-way instead of 4-way STS conflicts
    __shared__ float Bs[16][128];

    int tid = threadIdx.x;
    int bm = blockIdx.y * 128;
    int bn = blockIdx.x * 128;

    int a_row = tid >> 2;          // 0..63
    int a_col = (tid & 3) << 2;    // 0,4,8,12
    int b_row = tid >> 5;          // 0..7
    int b_col = (tid & 31) << 2;   // 0..124

    int tx = tid & 15;
    int ty = tid >> 4;

    float acc[8][8] = {};

    const float* Aptr  = A + (size_t)(bm + a_row) * K + a_col;
    const float* Aptr2 = Aptr + (size_t)64 * K;
    const float* Bptr  = B + (size_t)b_row * N + bn + b_col;

    for (int k0 = 0; k0 < K; k0 += 16) {
        float4 a0 = *(const float4*)(Aptr  + k0);
        float4 a1 = *(const float4*)(Aptr2 + k0);
        float4 b0 = *(const float4*)(Bptr + (size_t)k0 * N);
        float4 b1 = *(const float4*)(Bptr + (size_t)(k0 + 8) * N);

        As[a_col + 0][a_row] = a0.x;
        As[a_col + 1][a_row] = a0.y;
        As[a_col + 2][a_row] = a0.z;
        As[a_col + 3][a_row] = a0.w;
        As[a_col + 0][a_row + 64] = a1.x;
        As[a_col + 1][a_row + 64] = a1.y;
        As[a_col + 2][a_row + 64] = a1.z;
        As[a_col + 3][a_row + 64] = a1.w;
        *(float4*)&Bs[b_row][b_col]     = b0;
        *(float4*)&Bs[b_row + 8][b_col] = b1;
        __syncthreads();

        #pragma unroll
        for (int k = 0; k < 16; k++) {
            float af[8], bf[8];
            *(float4*)&af[0] = *(const float4*)&As[k][ty * 8];
            *(float4*)&af[4] = *(const float4*)&As[k][ty * 8 + 4];
            *(float4*)&bf[0] = *(const float4*)&Bs[k][tx * 8];
            *(float4*)&bf[4] = *(const float4*)&Bs[k][tx * 8 + 4];
            #pragma unroll
            for (int i = 0; i < 8; i++)
                #pragma unroll
                for (int j = 0; j < 8; j++)
                    acc[i][j] += af[i] * bf[j];
        }
        __syncthreads();
    }

    // Epilogue: column c -> h = c/192, d = (c%192)/3, r = c%3 (q/k/v)
    #pragma unroll
    for (int i = 0; i < 8; i++) {
        int m = bm + ty * 8 + i;
        int b = m >> 11;           // /2048
        int s = m & 2047;
        #pragma unroll
        for (int j = 0; j < 8; j++) {
            int c = bn + tx * 8 + j;
            int r = c % 3;
            int h = c / 192;
            int dd = (c % 192) / 3;
            float* dst = (r == 0) ? g_Q : (r == 1 ? g_K : g_V);
            dst[(((size_t)(b * NH + h)) * SEQ + s) * DH + dd] = acc[i][j];
        }
    }
}

// ---------------------------------------------------------------------------
// Flash attention (fp32). One thread per query row; K/V tiles (32 x 64) in
// smem, read via broadcast LDS.128. Online softmax.
// grid: (BH, SEQ/128), block: 128
// ---------------------------------------------------------------------------
__global__ __launch_bounds__(128) void flash_attn_kernel()
{
    __shared__ float Ks[32][64];
    __shared__ float Vs[32][64];

    int bh  = blockIdx.x;              // 0..31
    int q   = blockIdx.y * 128 + threadIdx.x;
    int tid = threadIdx.x;

    const float* Qp   = g_Q + ((size_t)bh * SEQ + q) * DH;
    const float* Kbas = g_K + (size_t)bh * SEQ * DH;
    const float* Vbas = g_V + (size_t)bh * SEQ * DH;

    float qreg[DH];
    #pragma unroll
    for (int d4 = 0; d4 < DH; d4 += 4) {
        float4 v = *(const float4*)(Qp + d4);
        qreg[d4 + 0] = v.x * 0.125f;   // fold 1/sqrt(64)
        qreg[d4 + 1] = v.y * 0.125f;
        qreg[d4 + 2] = v.z * 0.125f;
        qreg[d4 + 3] = v.w * 0.125f;
    }

    float o[DH];
    #pragma unroll
    for (int d = 0; d < DH; d++) o[d] = 0.0f;
    float mmax = -1e30f;
    float l = 0.0f;

    int lr = tid >> 2;             // 0..31 tile row
    int lc = (tid & 3) * 16;       // 0,16,32,48

    for (int kt = 0; kt < SEQ; kt += 32) {
        // cooperative load of K/V tiles
        {
            const float4* sk = (const float4*)(Kbas + (size_t)(kt + lr) * DH + lc);
            const float4* sv = (const float4*)(Vbas + (size_t)(kt + lr) * DH + lc);
            float4* dk = (float4*)&Ks[lr][lc];
            float4* dv = (float4*)&Vs[lr][lc];
            dk[0] = sk[0]; dk[1] = sk[1]; dk[2] = sk[2]; dk[3] = sk[3];
            dv[0] = sv[0]; dv[1] = sv[1]; dv[2] = sv[2]; dv[3] = sv[3];
        }
        __syncthreads();

        float sc[32];
        float tmax = mmax;
        #pragma unroll 1
        for (int j = 0; j < 32; j++) {
            const float4* kr = (const float4*)&Ks[j][0];
            float acc = 0.0f;
            #pragma unroll
            for (int d4 = 0; d4 < 16; d4++) {
                float4 kv = kr[d4];
                acc += qreg[4 * d4 + 0] * kv.x;
                acc += qreg[4 * d4 + 1] * kv.y;
                acc += qreg[4 * d4 + 2] * kv.z;
                acc += qreg[4 * d4 + 3] * kv.w;
            }
            sc[j] = acc;
            tmax = fmaxf(tmax, acc);
        }

        float corr = __expf(mmax - tmax);
        mmax = tmax;
        l *= corr;
        #pragma unroll
        for (int d = 0; d < DH; d++) o[d] *= corr;

        #pragma unroll 1
        for (int j = 0; j < 32; j++) {
            float p = __expf(sc[j] - mmax);
            l += p;
            const float4* vr = (const float4*)&Vs[j][0];
            #pragma unroll
            for (int d4 = 0; d4 < 16; d4++) {
                float4 vv = vr[d4];
                o[4 * d4 + 0] += p * vv.x;
                o[4 * d4 + 1] += p * vv.y;
                o[4 * d4 + 2] += p * vv.z;
                o[4 * d4 + 3] += p * vv.w;
            }
        }
        __syncthreads();
    }

    float inv = 1.0f / l;
    int b = bh >> 4;
    int h = bh & 15;
    float* Ap = g_A + (((size_t)b * SEQ + q) * NH + h) * DH;
    #pragma unroll
    for (int d4 = 0; d4 < DH; d4 += 4) {
        float4 v;
        v.x = o[d4 + 0] * inv;
        v.y = o[d4 + 1] * inv;
        v.z = o[d4 + 2] * inv;
        v.w = o[d4 + 3] * inv;
        *(float4*)(Ap + d4) = v;
    }
}

// ---------------------------------------------------------------------------
// GEMM 2: out = A_attn[4096,1024] @ W_out[1024,1024]
// ---------------------------------------------------------------------------
__global__ __launch_bounds__(256) void out_gemm_kernel(
    const float* __restrict__ B, float* __restrict__ C)
{
    const int K = D_MODEL;
    const int N = D_MODEL;
    const float* A = g_A;
    __shared__ float As[16][132];
    __shared__ float Bs[16][128];

    int tid = threadIdx.x;
    int bm = blockIdx.y * 128;
    int bn = blockIdx.x * 128;

    int a_row = tid >> 2;
    int a_col = (tid & 3) << 2;
    int b_row = tid >> 5;
    int b_col = (tid & 31) << 2;

    int tx = tid & 15;
    int ty = tid >> 4;

    float acc[8][8] = {};

    const float* Aptr  = A + (size_t)(bm + a_row) * K + a_col;
    const float* Aptr2 = Aptr + (size_t)64 * K;
    const float* Bptr  = B + (size_t)b_row * N + bn + b_col;

    for (int k0 = 0; k0 < K; k0 += 16) {
        float4 a0 = *(const float4*)(Aptr  + k0);
        float4 a1 = *(const float4*)(Aptr2 + k0);
        float4 b0 = *(const float4*)(Bptr + (size_t)k0 * N);
        float4 b1 = *(const float4*)(Bptr + (size_t)(k0 + 8) * N);

        As[a_col + 0][a_row] = a0.x;
        As[a_col + 1][a_row] = a0.y;
        As[a_col + 2][a_row] = a0.z;
        As[a_col + 3][a_row] = a0.w;
        As[a_col + 0][a_row + 64] = a1.x;
        As[a_col + 1][a_row + 64] = a1.y;
        As[a_col + 2][a_row + 64] = a1.z;
        As[a_col + 3][a_row + 64] = a1.w;
        *(float4*)&Bs[b_row][b_col]     = b0;
        *(float4*)&Bs[b_row + 8][b_col] = b1;
        __syncthreads();

        #pragma unroll
        for (int k = 0; k < 16; k++) {
            float af[8], bf[8];
            *(float4*)&af[0] = *(const float4*)&As[k][ty * 8];
            *(float4*)&af[4] = *(const float4*)&As[k][ty * 8 + 4];
            *(float4*)&bf[0] = *(const float4*)&Bs[k][tx * 8];
            *(float4*)&bf[4] = *(const float4*)&Bs[k][tx * 8 + 4];
            #pragma unroll
            for (int i = 0; i < 8; i++)
                #pragma unroll
                for (int j = 0; j < 8; j++)
                    acc[i][j] += af[i] * bf[j];
        }
        __syncthreads();
    }

    #pragma unroll
    for (int i = 0; i < 8; i++) {
        int m = bm + ty * 8 + i;
        float* Cp = C + (size_t)m * N + bn + tx * 8;
        float4 v0, v1;
        v0.x = acc[i][0]; v0.y = acc[i][1]; v0.z = acc[i][2]; v0.w = acc[i][3];
        v1.x = acc[i][4]; v1.y = acc[i][5]; v1.z = acc[i][6]; v1.w = acc[i][7];
        *(float4*)Cp       = v0;
        *(float4*)(Cp + 4) = v1;
    }
}

extern "C" void kernel_launch(void* const* d_in, const int* in_sizes, int n_in,
                              void* d_out, int out_size)
{
    const float* X     = (const float*)d_in[0];
    const float* W_qkv = (const float*)d_in[1];
    const float* W_out = (const float*)d_in[2];
    float* out = (float*)d_out;

    qkv_gemm_kernel<<<dim3(N_QKV / 128, M_ROWS / 128), 256>>>(X, W_qkv);
    flash_attn_kernel<<<dim3(BH, SEQ / 128), 128>>>();
    out_gemm_kernel<<<dim3(D_MODEL / 128, M_ROWS / 128), 256>>>(W_out, out);
}